// round 14
// baseline (speedup 1.0000x reference)
#include <cuda_runtime.h>
#include <math.h>

#define EPS_V    1e-6f
#define MARGIN_V 1.0f

// Scratch (allocation-free rule: __device__ globals)
__device__ float g_dan[50048];   // per-row d_an (200KB, L2-resident for K2)

// ---------------------------------------------------------------------------
// K1: pure streaming. One warp per negative row, 8 warps/block.
// Writes d_an[row] and retires immediately — no reductions, no atomics.
// ---------------------------------------------------------------------------
__global__ void __launch_bounds__(256) dan_kernel(
        const float* __restrict__ anchor,
        const float* __restrict__ neg,
        int D, int R) {
    extern __shared__ float4 s_a4[];           // D/4 float4 of anchor

    const int D4   = D >> 2;
    const int lane = threadIdx.x & 31;
    const int wid  = threadIdx.x >> 5;

    // stage anchor into smem (vectorized)
    const float4* __restrict__ a4 = (const float4*)anchor;
    for (int i = threadIdx.x; i < D4; i += blockDim.x) s_a4[i] = a4[i];
    __syncthreads();

    const int row = blockIdx.x * 8 + wid;
    if (row >= R) return;

    const float4* __restrict__ x4 = (const float4*)(neg + (size_t)row * D);
    float ss = 0.0f;
    #pragma unroll 4
    for (int i = lane; i < D4; i += 32) {
        float4 x = x4[i];
        float4 a = s_a4[i];
        float d0 = a.x - x.x + EPS_V;
        float d1 = a.y - x.y + EPS_V;
        float d2 = a.z - x.z + EPS_V;
        float d3 = a.w - x.w + EPS_V;
        ss = fmaf(d0, d0, ss);
        ss = fmaf(d1, d1, ss);
        ss = fmaf(d2, d2, ss);
        ss = fmaf(d3, d3, ss);
    }
    #pragma unroll
    for (int off = 16; off > 0; off >>= 1)
        ss += __shfl_xor_sync(0xffffffffu, ss, off);
    if (lane == 0) g_dan[row] = sqrtf(ss);
}

// ---------------------------------------------------------------------------
// K2: single block. Computes d_ap (warp p -> positive p), then reduces
// relu(d_ap[r%P] - d_an[r] + margin) over all rows in a fixed, deterministic
// order. d_an reads are L2 hits (just written by K1).
// ---------------------------------------------------------------------------
__global__ void __launch_bounds__(1024) finish_kernel(
        const float* __restrict__ anchor,
        const float* __restrict__ pos,
        float* __restrict__ out,
        int D, int R, int P) {
    __shared__ float s_dap[32];
    __shared__ float s_red[32];

    const int lane = threadIdx.x & 31;
    const int wid  = threadIdx.x >> 5;
    const int D4   = D >> 2;

    // --- d_ap: warp p handles positive p ---
    if (wid < P) {
        const float4* __restrict__ a4 = (const float4*)anchor;
        const float4* __restrict__ x4 = (const float4*)(pos + (size_t)wid * D);
        float ss = 0.0f;
        for (int i = lane; i < D4; i += 32) {
            float4 x = x4[i];
            float4 a = a4[i];
            float d0 = a.x - x.x + EPS_V;
            float d1 = a.y - x.y + EPS_V;
            float d2 = a.z - x.z + EPS_V;
            float d3 = a.w - x.w + EPS_V;
            ss = fmaf(d0, d0, ss);
            ss = fmaf(d1, d1, ss);
            ss = fmaf(d2, d2, ss);
            ss = fmaf(d3, d3, ss);
        }
        #pragma unroll
        for (int off = 16; off > 0; off >>= 1)
            ss += __shfl_xor_sync(0xffffffffu, ss, off);
        if (lane == 0) s_dap[wid] = sqrtf(ss);
    }
    __syncthreads();

    // --- relu + reduce (fixed per-thread partitions -> deterministic) ---
    float acc = 0.0f;
    for (int r = threadIdx.x; r < R; r += blockDim.x) {
        float t = s_dap[r % P] - g_dan[r] + MARGIN_V;
        acc += fmaxf(t, 0.0f);
    }
    #pragma unroll
    for (int off = 16; off > 0; off >>= 1)
        acc += __shfl_xor_sync(0xffffffffu, acc, off);
    if (lane == 0) s_red[wid] = acc;
    __syncthreads();
    if (threadIdx.x == 0) {
        float tot = 0.0f;
        #pragma unroll
        for (int w = 0; w < 32; ++w) tot += s_red[w];
        out[0] = tot;
    }
}

// ---------------------------------------------------------------------------
extern "C" void kernel_launch(void* const* d_in, const int* in_sizes, int n_in,
                              void* d_out, int out_size) {
    const float* anchor = (const float*)d_in[0];
    const float* pos    = (const float*)d_in[1];
    const float* neg    = (const float*)d_in[2];
    float* out          = (float*)d_out;

    const int D = in_sizes[0];            // 2400
    const int P = in_sizes[1] / D;        // 5
    const int N = in_sizes[2] / D;        // 50000
    const int C = N / P;                  // 10000
    const int R = C * P;                  // 50000 rows used

    const int nBlocks = (R + 7) / 8;      // 6250: one row per warp
    const size_t smem = (size_t)(D >> 2) * sizeof(float4);
    dan_kernel<<<nBlocks, 256, smem>>>(anchor, neg, D, R);
    finish_kernel<<<1, 1024>>>(anchor, pos, out, D, R, P);
}

// round 15
// speedup vs baseline: 1.1864x; 1.1864x over previous
#include <cuda_runtime.h>
#include <math.h>

#define EPS_V    1e-6f
#define MARGIN_V 1.0f

// Scratch (allocation-free rule: __device__ globals)
__device__ float        g_dan[50048];     // per-row d_an (200KB, L2-resident)
__device__ float        g_partials[64];
__device__ unsigned int g_count = 0;      // reset by last block each launch

// ---------------------------------------------------------------------------
// K1: pure streaming (UNCHANGED — 7.0 TB/s). One warp per negative row.
// ---------------------------------------------------------------------------
__global__ void __launch_bounds__(256) dan_kernel(
        const float* __restrict__ anchor,
        const float* __restrict__ neg,
        int D, int R) {
    extern __shared__ float4 s_a4[];           // D/4 float4 of anchor

    const int D4   = D >> 2;
    const int lane = threadIdx.x & 31;
    const int wid  = threadIdx.x >> 5;

    const float4* __restrict__ a4 = (const float4*)anchor;
    for (int i = threadIdx.x; i < D4; i += blockDim.x) s_a4[i] = a4[i];
    __syncthreads();

    const int row = blockIdx.x * 8 + wid;
    if (row >= R) return;

    const float4* __restrict__ x4 = (const float4*)(neg + (size_t)row * D);
    float ss = 0.0f;
    #pragma unroll 4
    for (int i = lane; i < D4; i += 32) {
        float4 x = x4[i];
        float4 a = s_a4[i];
        float d0 = a.x - x.x + EPS_V;
        float d1 = a.y - x.y + EPS_V;
        float d2 = a.z - x.z + EPS_V;
        float d3 = a.w - x.w + EPS_V;
        ss = fmaf(d0, d0, ss);
        ss = fmaf(d1, d1, ss);
        ss = fmaf(d2, d2, ss);
        ss = fmaf(d3, d3, ss);
    }
    #pragma unroll
    for (int off = 16; off > 0; off >>= 1)
        ss += __shfl_xor_sync(0xffffffffu, ss, off);
    if (lane == 0) g_dan[row] = sqrtf(ss);
}

// ---------------------------------------------------------------------------
// K2: 64-block epilogue. Each block redundantly computes d_ap (L2 hits),
// reduces its fixed slice of g_dan with relu, writes its partial; the
// last-arriving block sums the 64 partials in fixed order -> out[0].
// ---------------------------------------------------------------------------
__global__ void __launch_bounds__(256) finish_kernel(
        const float* __restrict__ anchor,
        const float* __restrict__ pos,
        float* __restrict__ out,
        int D, int R, int P, int nBlocks) {
    __shared__ float s_dap[8];
    __shared__ float s_red[8];
    __shared__ bool  s_last;

    const int lane = threadIdx.x & 31;
    const int wid  = threadIdx.x >> 5;
    const int D4   = D >> 2;

    // --- d_ap: warp p handles positive p (redundant per block, L2 hits) ---
    if (wid < P) {
        const float4* __restrict__ a4 = (const float4*)anchor;
        const float4* __restrict__ x4 = (const float4*)(pos + (size_t)wid * D);
        float ss = 0.0f;
        for (int i = lane; i < D4; i += 32) {
            float4 x = x4[i];
            float4 a = a4[i];
            float d0 = a.x - x.x + EPS_V;
            float d1 = a.y - x.y + EPS_V;
            float d2 = a.z - x.z + EPS_V;
            float d3 = a.w - x.w + EPS_V;
            ss = fmaf(d0, d0, ss);
            ss = fmaf(d1, d1, ss);
            ss = fmaf(d2, d2, ss);
            ss = fmaf(d3, d3, ss);
        }
        #pragma unroll
        for (int off = 16; off > 0; off >>= 1)
            ss += __shfl_xor_sync(0xffffffffu, ss, off);
        if (lane == 0) s_dap[wid] = sqrtf(ss);
    }
    __syncthreads();

    // --- relu + reduce over this block's fixed slice (deterministic) ---
    const int chunk = (R + nBlocks - 1) / nBlocks;
    const int r0    = blockIdx.x * chunk;
    const int r1    = min(R, r0 + chunk);

    float acc = 0.0f;
    for (int r = r0 + threadIdx.x; r < r1; r += blockDim.x) {
        float t = s_dap[r % P] - g_dan[r] + MARGIN_V;
        acc += fmaxf(t, 0.0f);
    }
    #pragma unroll
    for (int off = 16; off > 0; off >>= 1)
        acc += __shfl_xor_sync(0xffffffffu, acc, off);
    if (lane == 0) s_red[wid] = acc;
    __syncthreads();

    if (threadIdx.x == 0) {
        float tot = 0.0f;
        #pragma unroll
        for (int w = 0; w < 8; ++w) tot += s_red[w];
        g_partials[blockIdx.x] = tot;
        __threadfence();
        unsigned int old = atomicAdd(&g_count, 1u);
        s_last = (old == (unsigned)(nBlocks - 1));
    }
    __syncthreads();

    // --- last block: fixed-order final sum + counter reset ---
    if (s_last && threadIdx.x == 0) {
        __threadfence();
        float tot = 0.0f;
        for (int b = 0; b < nBlocks; ++b) tot += g_partials[b];
        out[0] = tot;
        g_count = 0;                       // reset for next graph replay
    }
}

// ---------------------------------------------------------------------------
extern "C" void kernel_launch(void* const* d_in, const int* in_sizes, int n_in,
                              void* d_out, int out_size) {
    const float* anchor = (const float*)d_in[0];
    const float* pos    = (const float*)d_in[1];
    const float* neg    = (const float*)d_in[2];
    float* out          = (float*)d_out;

    const int D = in_sizes[0];            // 2400
    const int P = in_sizes[1] / D;        // 5
    const int N = in_sizes[2] / D;        // 50000
    const int C = N / P;                  // 10000
    const int R = C * P;                  // 50000 rows used

    const int nBlocks = (R + 7) / 8;      // 6250: one row per warp
    const size_t smem = (size_t)(D >> 2) * sizeof(float4);
    dan_kernel<<<nBlocks, 256, smem>>>(anchor, neg, D, R);

    const int fBlocks = 64;
    finish_kernel<<<fBlocks, 256>>>(anchor, pos, out, D, R, P, fBlocks);
}

// round 16
// speedup vs baseline: 1.2830x; 1.0814x over previous
#include <cuda_runtime.h>
#include <math.h>

#define EPS_V    1e-6f
#define MARGIN_V 1.0f

// Scratch (allocation-free rule: __device__ globals)
__device__ float        g_dap[64];
__device__ float        g_dan[50048];     // per-row d_an (200KB, L2-resident)
__device__ float        g_partials[64];
__device__ unsigned int g_count = 0;      // reset by last block each launch

// ---------------------------------------------------------------------------
// K1: blocks 0..P-1 compute d_ap[p] (overlapped, wave 1); blocks P.. stream
// one negative row per warp (unchanged 7.0 TB/s hot path).
// ---------------------------------------------------------------------------
__global__ void __launch_bounds__(256) dan_kernel(
        const float* __restrict__ anchor,
        const float* __restrict__ pos,
        const float* __restrict__ neg,
        int D, int R, int P) {
    extern __shared__ float4 s_a4[];           // D/4 float4 of anchor
    __shared__ float s_red[8];

    const int D4   = D >> 2;
    const int lane = threadIdx.x & 31;
    const int wid  = threadIdx.x >> 5;

    // stage anchor into smem (vectorized) — both paths use it
    const float4* __restrict__ a4 = (const float4*)anchor;
    for (int i = threadIdx.x; i < D4; i += blockDim.x) s_a4[i] = a4[i];
    __syncthreads();

    if (blockIdx.x < (unsigned)P) {
        // --- cold path: whole block computes d_ap[blockIdx] ---
        const int p = blockIdx.x;
        const float4* __restrict__ x4 = (const float4*)(pos + (size_t)p * D);
        float ss = 0.0f;
        for (int i = threadIdx.x; i < D4; i += blockDim.x) {
            float4 x = x4[i];
            float4 a = s_a4[i];
            float d0 = a.x - x.x + EPS_V;
            float d1 = a.y - x.y + EPS_V;
            float d2 = a.z - x.z + EPS_V;
            float d3 = a.w - x.w + EPS_V;
            ss = fmaf(d0, d0, ss);
            ss = fmaf(d1, d1, ss);
            ss = fmaf(d2, d2, ss);
            ss = fmaf(d3, d3, ss);
        }
        #pragma unroll
        for (int off = 16; off > 0; off >>= 1)
            ss += __shfl_xor_sync(0xffffffffu, ss, off);
        if (lane == 0) s_red[wid] = ss;
        __syncthreads();
        if (threadIdx.x == 0) {
            float tot = 0.0f;
            #pragma unroll
            for (int w = 0; w < 8; ++w) tot += s_red[w];
            g_dap[p] = sqrtf(tot);
        }
        return;
    }

    // --- hot path: one warp per negative row (unchanged) ---
    const int row = (blockIdx.x - P) * 8 + wid;
    if (row >= R) return;

    const float4* __restrict__ x4 = (const float4*)(neg + (size_t)row * D);
    float ss = 0.0f;
    #pragma unroll 4
    for (int i = lane; i < D4; i += 32) {
        float4 x = x4[i];
        float4 a = s_a4[i];
        float d0 = a.x - x.x + EPS_V;
        float d1 = a.y - x.y + EPS_V;
        float d2 = a.z - x.z + EPS_V;
        float d3 = a.w - x.w + EPS_V;
        ss = fmaf(d0, d0, ss);
        ss = fmaf(d1, d1, ss);
        ss = fmaf(d2, d2, ss);
        ss = fmaf(d3, d3, ss);
    }
    #pragma unroll
    for (int off = 16; off > 0; off >>= 1)
        ss += __shfl_xor_sync(0xffffffffu, ss, off);
    if (lane == 0) g_dan[row] = sqrtf(ss);
}

// ---------------------------------------------------------------------------
// K2: tiny epilogue. 64 blocks; each reduces a fixed slice of g_dan with relu
// using the precomputed g_dap (all L2 hits); last block sums partials in
// fixed order -> out[0] and resets the counter.
// ---------------------------------------------------------------------------
__global__ void __launch_bounds__(256) finish_kernel(
        float* __restrict__ out,
        int R, int P, int nBlocks) {
    __shared__ float s_dap[8];
    __shared__ float s_red[8];
    __shared__ bool  s_last;

    const int lane = threadIdx.x & 31;
    const int wid  = threadIdx.x >> 5;

    if (threadIdx.x < (unsigned)P) s_dap[threadIdx.x] = g_dap[threadIdx.x];
    __syncthreads();

    // relu + reduce over this block's fixed slice (deterministic)
    const int chunk = (R + nBlocks - 1) / nBlocks;
    const int r0    = blockIdx.x * chunk;
    const int r1    = min(R, r0 + chunk);

    float acc = 0.0f;
    for (int r = r0 + threadIdx.x; r < r1; r += blockDim.x) {
        float t = s_dap[r % P] - g_dan[r] + MARGIN_V;
        acc += fmaxf(t, 0.0f);
    }
    #pragma unroll
    for (int off = 16; off > 0; off >>= 1)
        acc += __shfl_xor_sync(0xffffffffu, acc, off);
    if (lane == 0) s_red[wid] = acc;
    __syncthreads();

    if (threadIdx.x == 0) {
        float tot = 0.0f;
        #pragma unroll
        for (int w = 0; w < 8; ++w) tot += s_red[w];
        g_partials[blockIdx.x] = tot;
        __threadfence();
        unsigned int old = atomicAdd(&g_count, 1u);
        s_last = (old == (unsigned)(nBlocks - 1));
    }
    __syncthreads();

    if (s_last && threadIdx.x == 0) {
        __threadfence();
        float tot = 0.0f;
        for (int b = 0; b < nBlocks; ++b) tot += g_partials[b];
        out[0] = tot;
        g_count = 0;                       // reset for next graph replay
    }
}

// ---------------------------------------------------------------------------
extern "C" void kernel_launch(void* const* d_in, const int* in_sizes, int n_in,
                              void* d_out, int out_size) {
    const float* anchor = (const float*)d_in[0];
    const float* pos    = (const float*)d_in[1];
    const float* neg    = (const float*)d_in[2];
    float* out          = (float*)d_out;

    const int D = in_sizes[0];            // 2400
    const int P = in_sizes[1] / D;        // 5
    const int N = in_sizes[2] / D;        // 50000
    const int C = N / P;                  // 10000
    const int R = C * P;                  // 50000 rows used

    const int nBlocks = P + (R + 7) / 8;  // 5 dap blocks + 6250 streaming blocks
    const size_t smem = (size_t)(D >> 2) * sizeof(float4);
    dan_kernel<<<nBlocks, 256, smem>>>(anchor, pos, neg, D, R, P);

    const int fBlocks = 64;
    finish_kernel<<<fBlocks, 256>>>(out, R, P, fBlocks);
}